// round 12
// baseline (speedup 1.0000x reference)
#include <cuda_runtime.h>
#include <cuda_bf16.h>
#include <math.h>
#include <stdint.h>

// ---------------- problem dims ----------------
#define BB 2
#define TT 1024
#define DD 768
#define HH 12
#define DH 64
#define NTOK (BB*TT)          // 2048
#define PH 4
#define NK 256
#define TOPK 32
#define DHK 128
#define DQ (PH*DHK*2)         // 1024
#define EPS 1e-5f

// ---------------- scratch ----------------
__device__ float g_h1[NTOK*DD];
__device__ float g_q[NTOK*DD];
__device__ float g_k[NTOK*DD];
__device__ float g_v[NTOK*DD];
__device__ float g_ctx[NTOK*DD];
__device__ float g_x1[NTOK*DD];
__device__ float g_h2[NTOK*DD];
__device__ float g_qf[NTOK*DQ];
__device__ float g_qn[NTOK*DQ];
__device__ float g_mu[DQ];
__device__ float g_rstd[DQ];
__device__ float g_dots[PH*2*NTOK*NK];
__device__ float g_s1[NTOK*8*TOPK];
__device__ int   g_i1[NTOK*8*TOPK];
__device__ float g_attn[NTOK*PH*TOPK];
__device__ int   g_vi[NTOK*PH*TOPK];

__device__ __forceinline__ uint32_t f2tf32(float f) {
    uint32_t o;
    asm("cvt.rna.tf32.f32 %0, %1;" : "=r"(o) : "f"(f));
    return o;
}

#define MMA_TF32(d0,d1,d2,d3,a0,a1,a2,a3,b0,b1) \
    asm volatile( \
        "mma.sync.aligned.m16n8k8.row.col.f32.tf32.tf32.f32 " \
        "{%0,%1,%2,%3}, {%4,%5,%6,%7}, {%8,%9}, {%0,%1,%2,%3};" \
        : "+f"(d0), "+f"(d1), "+f"(d2), "+f"(d3) \
        : "r"(a0), "r"(a1), "r"(a2), "r"(a3), "r"(b0), "r"(b1))

extern __shared__ uint32_t dyn_smem[];

// ====== mma.sync tf32 GEMM (256 thr, single-buffered, 2 CTAs/SM co-resident) ======
// C = A @ B (+bias)(+res). TB: B stored [N,K]. CTA tile 128x128, BK=32.
// 8 warps (4x2), each 32 rows x 64 cols. Smem 36.9KB + <=128 regs -> 2 CTAs/SM,
// so latency-bound k-loops of co-resident CTAs overlap (QKV/dots become 1 wave).
// NSEL==3: blockIdx.z selects (B,bias,C) triple (fused QKV). NSEL==1: 2-level z batch.
#define GEMM_SMEM ((128*36 + 128*36) * 4)   // 36864 bytes

template<bool TB, int NSEL>
__global__ void __launch_bounds__(256, 2) gemm_mma(
    const float* __restrict__ A,
    const float* __restrict__ B0, const float* __restrict__ B1, const float* __restrict__ B2,
    const float* __restrict__ bias0, const float* __restrict__ bias1, const float* __restrict__ bias2,
    const float* __restrict__ res,
    float* __restrict__ C0, float* __restrict__ C1, float* __restrict__ C2,
    int K, int lda, int ldb, int ldc,
    int zDiv, long aO, long aI, long bO, long bI, long cO, long cI)
{
    uint32_t* As = dyn_smem;            // [128][36]
    uint32_t* Bs = dyn_smem + 128 * 36; // [128][36]

    int tid = threadIdx.x;
    const float* Bm;
    const float* bias;
    float* C;
    if (NSEL == 3) {
        int s = blockIdx.z;
        Bm   = s == 0 ? B0 : (s == 1 ? B1 : B2);
        bias = s == 0 ? bias0 : (s == 1 ? bias1 : bias2);
        C    = s == 0 ? C0 : (s == 1 ? C1 : C2);
    } else {
        int z = blockIdx.z, zo = z / zDiv, zi = z - zo * zDiv;
        A  += (long)zo * aO + (long)zi * aI;
        Bm = B0 + (long)zo * bO + (long)zi * bI;
        long coff = (long)zo * cO + (long)zi * cI;
        C = C0 + coff;
        bias = bias0;
        if (res) res += coff;
    }

    int row0 = blockIdx.y * 128, col0 = blockIdx.x * 128;

    int wid = tid >> 5, lane = tid & 31;
    int g = lane >> 2, t = lane & 3;
    int wm = wid >> 1, wn = wid & 1;      // 4x2 warp grid
    int mbase = wm * 32, nbase = wn * 64; // 32x64 per warp

    float acc[2][8][4];
    #pragma unroll
    for (int i = 0; i < 2; i++)
        #pragma unroll
        for (int j = 0; j < 8; j++)
            #pragma unroll
            for (int q = 0; q < 4; q++) acc[i][j][q] = 0.f;

    int nt = K >> 5;
    for (int tt = 0; tt < nt; tt++) {
        int k0 = tt << 5;
        // stage tile tt into registers
        float4 ar[4];
        #pragma unroll
        for (int i = 0; i < 4; i++) {
            int idx = i * 256 + tid;
            int r = idx >> 3, c = (idx & 7) << 2;
            ar[i] = *(const float4*)(A + (long)(row0 + r) * lda + k0 + c);
        }
        float4 br[4];
        if (TB) {
            #pragma unroll
            for (int i = 0; i < 4; i++) {
                int idx = i * 256 + tid;
                int r = idx >> 3, c = (idx & 7) << 2;
                br[i] = *(const float4*)(Bm + (long)(col0 + r) * ldb + k0 + c);
            }
        } else {
            #pragma unroll
            for (int i = 0; i < 4; i++) {
                int idx = i * 256 + tid;             // f4 slot
                int nf = (idx & 31) << 2, kk = idx >> 5;
                br[i] = *(const float4*)(Bm + (long)(k0 + kk) * ldb + col0 + nf);
            }
        }
        if (tt) __syncthreads();   // previous compute done before overwrite
        #pragma unroll
        for (int i = 0; i < 4; i++) {
            int idx = i * 256 + tid;
            int r = idx >> 3, c = (idx & 7) << 2;
            As[r * 36 + c + 0] = f2tf32(ar[i].x);
            As[r * 36 + c + 1] = f2tf32(ar[i].y);
            As[r * 36 + c + 2] = f2tf32(ar[i].z);
            As[r * 36 + c + 3] = f2tf32(ar[i].w);
        }
        if (TB) {
            #pragma unroll
            for (int i = 0; i < 4; i++) {
                int idx = i * 256 + tid;
                int r = idx >> 3, c = (idx & 7) << 2;
                Bs[r * 36 + c + 0] = f2tf32(br[i].x);
                Bs[r * 36 + c + 1] = f2tf32(br[i].y);
                Bs[r * 36 + c + 2] = f2tf32(br[i].z);
                Bs[r * 36 + c + 3] = f2tf32(br[i].w);
            }
        } else {
            #pragma unroll
            for (int i = 0; i < 4; i++) {
                int idx = i * 256 + tid;
                int nf = (idx & 31) << 2, kk = idx >> 5;
                Bs[(nf + 0) * 36 + kk] = f2tf32(br[i].x);
                Bs[(nf + 1) * 36 + kk] = f2tf32(br[i].y);
                Bs[(nf + 2) * 36 + kk] = f2tf32(br[i].z);
                Bs[(nf + 3) * 36 + kk] = f2tf32(br[i].w);
            }
        }
        __syncthreads();

        #pragma unroll
        for (int ks = 0; ks < 4; ks++) {
            int kk0 = ks * 8;
            uint32_t af[2][4];
            #pragma unroll
            for (int i = 0; i < 2; i++) {
                int m0 = mbase + i * 16;
                af[i][0] = As[(m0 + g) * 36 + kk0 + t];
                af[i][1] = As[(m0 + g + 8) * 36 + kk0 + t];
                af[i][2] = As[(m0 + g) * 36 + kk0 + t + 4];
                af[i][3] = As[(m0 + g + 8) * 36 + kk0 + t + 4];
            }
            uint32_t bf[8][2];
            #pragma unroll
            for (int j = 0; j < 8; j++) {
                int n0 = nbase + j * 8;
                bf[j][0] = Bs[(n0 + g) * 36 + kk0 + t];
                bf[j][1] = Bs[(n0 + g) * 36 + kk0 + t + 4];
            }
            #pragma unroll
            for (int i = 0; i < 2; i++)
                #pragma unroll
                for (int j = 0; j < 8; j++)
                    MMA_TF32(acc[i][j][0], acc[i][j][1], acc[i][j][2], acc[i][j][3],
                             af[i][0], af[i][1], af[i][2], af[i][3],
                             bf[j][0], bf[j][1]);
        }
    }

    #pragma unroll
    for (int i = 0; i < 2; i++) {
        int r0 = row0 + mbase + i * 16 + g;
        #pragma unroll
        for (int j = 0; j < 8; j++) {
            int cc = col0 + nbase + j * 8 + t * 2;
            float2 bv = make_float2(0.f, 0.f);
            if (bias) bv = *(const float2*)(bias + cc);
            {
                long off = (long)r0 * ldc + cc;
                float2 o = make_float2(acc[i][j][0] + bv.x, acc[i][j][1] + bv.y);
                if (res) { float2 rv = *(const float2*)(res + off); o.x += rv.x; o.y += rv.y; }
                *(float2*)(C + off) = o;
            }
            {
                long off = (long)(r0 + 8) * ldc + cc;
                float2 o = make_float2(acc[i][j][2] + bv.x, acc[i][j][3] + bv.y);
                if (res) { float2 rv = *(const float2*)(res + off); o.x += rv.x; o.y += rv.y; }
                *(float2*)(C + off) = o;
            }
        }
    }
}

// ================= flash attention =================
#define LSQ 68
#define LSV 72
#define LSS 132
#define FLASH_SMEM ((128*LSQ + 128*LSQ + 128*LSV + 128*LSS + 3*128) * 4)

__global__ void __launch_bounds__(256, 1) flash_kernel(
    const float* __restrict__ q, const float* __restrict__ k,
    const float* __restrict__ v, float* __restrict__ ctx)
{
    uint32_t* Qs = dyn_smem;
    uint32_t* Ks = Qs + 128 * LSQ;
    uint32_t* Vs = Ks + 128 * LSQ;
    float*    Ss = (float*)(Vs + 128 * LSV);
    float*  rowm = Ss + 128 * LSS;
    float*  rowl = rowm + 128;
    float*  rowc = rowl + 128;

    int qt = blockIdx.x, bh = blockIdx.y;
    int b = bh / HH, h = bh % HH;
    const float* qp = q + ((long)b * TT + qt * 128) * DD + h * 64;
    const float* kp = k + (long)b * TT * DD + h * 64;
    const float* vp = v + (long)b * TT * DD + h * 64;
    float* op = ctx + ((long)b * TT + qt * 128) * DD + h * 64;

    int tid = threadIdx.x, wid = tid >> 5, lane = tid & 31;
    int g = lane >> 2, t = lane & 3;
    int wm = wid >> 1, wn = wid & 1;
    int mbase = wm * 32, nbaseS = wn * 64, nbaseO = wn * 32;

    #pragma unroll
    for (int i = 0; i < 8; i++) {
        int idx = i * 256 + tid;
        int r = idx >> 4, c = (idx & 15) << 2;
        float4 a = *(const float4*)(qp + (long)r * DD + c);
        Qs[r * LSQ + c + 0] = f2tf32(a.x);
        Qs[r * LSQ + c + 1] = f2tf32(a.y);
        Qs[r * LSQ + c + 2] = f2tf32(a.z);
        Qs[r * LSQ + c + 3] = f2tf32(a.w);
    }
    if (tid < 128) { rowm[tid] = -1e30f; rowl[tid] = 0.f; }

    float accO[2][4][4];
    #pragma unroll
    for (int i = 0; i < 2; i++)
        #pragma unroll
        for (int j = 0; j < 4; j++)
            #pragma unroll
            for (int e = 0; e < 4; e++) accO[i][j][e] = 0.f;

    for (int kt = 0; kt < 8; kt++) {
        const float* kq = kp + (long)kt * 128 * DD;
        const float* vq = vp + (long)kt * 128 * DD;
        #pragma unroll
        for (int i = 0; i < 8; i++) {
            int idx = i * 256 + tid;
            int r = idx >> 4, c = (idx & 15) << 2;
            float4 a = *(const float4*)(kq + (long)r * DD + c);
            Ks[r * LSQ + c + 0] = f2tf32(a.x);
            Ks[r * LSQ + c + 1] = f2tf32(a.y);
            Ks[r * LSQ + c + 2] = f2tf32(a.z);
            Ks[r * LSQ + c + 3] = f2tf32(a.w);
            float4 bvv = *(const float4*)(vq + (long)r * DD + c);
            Vs[r * LSV + c + 0] = f2tf32(bvv.x);
            Vs[r * LSV + c + 1] = f2tf32(bvv.y);
            Vs[r * LSV + c + 2] = f2tf32(bvv.z);
            Vs[r * LSV + c + 3] = f2tf32(bvv.w);
        }
        __syncthreads();

        float accS[2][8][4];
        #pragma unroll
        for (int i = 0; i < 2; i++)
            #pragma unroll
            for (int j = 0; j < 8; j++)
                #pragma unroll
                for (int e = 0; e < 4; e++) accS[i][j][e] = 0.f;
        #pragma unroll
        for (int ks = 0; ks < 8; ks++) {
            int k0 = ks * 8;
            uint32_t af[2][4];
            #pragma unroll
            for (int i = 0; i < 2; i++) {
                int m0 = mbase + i * 16;
                af[i][0] = Qs[(m0 + g) * LSQ + k0 + t];
                af[i][1] = Qs[(m0 + g + 8) * LSQ + k0 + t];
                af[i][2] = Qs[(m0 + g) * LSQ + k0 + t + 4];
                af[i][3] = Qs[(m0 + g + 8) * LSQ + k0 + t + 4];
            }
            uint32_t bf[8][2];
            #pragma unroll
            for (int j = 0; j < 8; j++) {
                int n0 = nbaseS + j * 8;
                bf[j][0] = Ks[(n0 + g) * LSQ + k0 + t];
                bf[j][1] = Ks[(n0 + g) * LSQ + k0 + t + 4];
            }
            #pragma unroll
            for (int i = 0; i < 2; i++)
                #pragma unroll
                for (int j = 0; j < 8; j++)
                    MMA_TF32(accS[i][j][0], accS[i][j][1], accS[i][j][2], accS[i][j][3],
                             af[i][0], af[i][1], af[i][2], af[i][3],
                             bf[j][0], bf[j][1]);
        }
        #pragma unroll
        for (int i = 0; i < 2; i++) {
            int r0 = mbase + i * 16 + g;
            #pragma unroll
            for (int j = 0; j < 8; j++) {
                int cc = nbaseS + j * 8 + t * 2;
                Ss[r0 * LSS + cc]           = accS[i][j][0] * 0.125f;
                Ss[r0 * LSS + cc + 1]       = accS[i][j][1] * 0.125f;
                Ss[(r0 + 8) * LSS + cc]     = accS[i][j][2] * 0.125f;
                Ss[(r0 + 8) * LSS + cc + 1] = accS[i][j][3] * 0.125f;
            }
        }
        __syncthreads();

        {
            int r = wid * 16 + (lane >> 1), half = lane & 1;
            float* srow = Ss + r * LSS + half * 64;
            float mx = -1e30f;
            #pragma unroll
            for (int ii = 0; ii < 16; ii++) {
                float4 a = *(float4*)(srow + ii * 4);
                mx = fmaxf(mx, fmaxf(fmaxf(a.x, a.y), fmaxf(a.z, a.w)));
            }
            mx = fmaxf(mx, __shfl_xor_sync(0xffffffffu, mx, 1));
            float mprev = rowm[r];
            float mnew = fmaxf(mprev, mx);
            float corr = __expf(mprev - mnew);
            float sum = 0.f;
            #pragma unroll
            for (int ii = 0; ii < 16; ii++) {
                float4 a = *(float4*)(srow + ii * 4);
                float p0 = __expf(a.x - mnew), p1 = __expf(a.y - mnew);
                float p2 = __expf(a.z - mnew), p3 = __expf(a.w - mnew);
                sum += p0 + p1 + p2 + p3;
                uint4 u;
                u.x = f2tf32(p0); u.y = f2tf32(p1);
                u.z = f2tf32(p2); u.w = f2tf32(p3);
                *(uint4*)(srow + ii * 4) = u;
            }
            sum += __shfl_xor_sync(0xffffffffu, sum, 1);
            if (half == 0) {
                rowm[r] = mnew;
                rowl[r] = rowl[r] * corr + sum;
                rowc[r] = corr;
            }
        }
        __syncthreads();

        float c0[2], c1[2];
        #pragma unroll
        for (int i = 0; i < 2; i++) {
            c0[i] = rowc[mbase + i * 16 + g];
            c1[i] = rowc[mbase + i * 16 + g + 8];
        }
        #pragma unroll
        for (int i = 0; i < 2; i++)
            #pragma unroll
            for (int j = 0; j < 4; j++) {
                accO[i][j][0] *= c0[i]; accO[i][j][1] *= c0[i];
                accO[i][j][2] *= c1[i]; accO[i][j][3] *= c1[i];
            }
        const uint32_t* Su = (const uint32_t*)Ss;
        #pragma unroll
        for (int ks = 0; ks < 16; ks++) {
            int k0 = ks * 8;
            uint32_t af[2][4];
            #pragma unroll
            for (int i = 0; i < 2; i++) {
                int m0 = mbase + i * 16;
                af[i][0] = Su[(m0 + g) * LSS + k0 + t];
                af[i][1] = Su[(m0 + g + 8) * LSS + k0 + t];
                af[i][2] = Su[(m0 + g) * LSS + k0 + t + 4];
                af[i][3] = Su[(m0 + g + 8) * LSS + k0 + t + 4];
            }
            uint32_t bf[4][2];
            #pragma unroll
            for (int j = 0; j < 4; j++) {
                int n0 = nbaseO + j * 8;
                bf[j][0] = Vs[(k0 + t) * LSV + n0 + g];
                bf[j][1] = Vs[(k0 + t + 4) * LSV + n0 + g];
            }
            #pragma unroll
            for (int i = 0; i < 2; i++)
                #pragma unroll
                for (int j = 0; j < 4; j++)
                    MMA_TF32(accO[i][j][0], accO[i][j][1], accO[i][j][2], accO[i][j][3],
                             af[i][0], af[i][1], af[i][2], af[i][3],
                             bf[j][0], bf[j][1]);
        }
        __syncthreads();
    }

    #pragma unroll
    for (int i = 0; i < 2; i++) {
        int r0 = mbase + i * 16 + g;
        float inv0 = 1.f / rowl[r0];
        float inv1 = 1.f / rowl[r0 + 8];
        #pragma unroll
        for (int j = 0; j < 4; j++) {
            int cc = nbaseO + j * 8 + t * 2;
            float2 o0 = make_float2(accO[i][j][0] * inv0, accO[i][j][1] * inv0);
            float2 o1 = make_float2(accO[i][j][2] * inv1, accO[i][j][3] * inv1);
            *(float2*)(op + (long)r0 * DD + cc) = o0;
            *(float2*)(op + (long)(r0 + 8) * DD + cc) = o1;
        }
    }
}

// ---------------- LayerNorm ----------------
__global__ void ln_kernel(const float* __restrict__ x, const float* __restrict__ g,
                          const float* __restrict__ b, float* __restrict__ out) {
    int n = blockIdx.x;
    int tid = threadIdx.x;
    const float* xr = x + (long)n * DD;
    float v0 = xr[tid], v1 = xr[tid + 256], v2 = xr[tid + 512];
    float s = v0 + v1 + v2;
    float sq = v0*v0 + v1*v1 + v2*v2;
    for (int off = 16; off; off >>= 1) {
        s  += __shfl_xor_sync(0xffffffffu, s, off);
        sq += __shfl_xor_sync(0xffffffffu, sq, off);
    }
    __shared__ float shs[8], shq[8];
    __shared__ float sm, sr;
    int w = tid >> 5, lane = tid & 31;
    if (lane == 0) { shs[w] = s; shq[w] = sq; }
    __syncthreads();
    if (tid == 0) {
        float ts = 0.f, tq = 0.f;
        #pragma unroll
        for (int i = 0; i < 8; i++) { ts += shs[i]; tq += shq[i]; }
        float m = ts / (float)DD;
        float var = tq / (float)DD - m * m;
        sm = m;
        sr = rsqrtf(var + EPS);
    }
    __syncthreads();
    float m = sm, rr = sr;
    float* o = out + (long)n * DD;
    o[tid]       = (v0 - m) * rr * g[tid]       + b[tid];
    o[tid + 256] = (v1 - m) * rr * g[tid + 256] + b[tid + 256];
    o[tid + 512] = (v2 - m) * rr * g[tid + 512] + b[tid + 512];
}

// ---------------- BatchNorm ----------------
__global__ void bn_stats_kernel(const float* __restrict__ qf,
                                float* __restrict__ mu, float* __restrict__ rstd) {
    int lane = threadIdx.x & 31;
    int w = threadIdx.x >> 5;
    int c = blockIdx.x * 32 + lane;
    float s = 0.f, sq = 0.f;
    for (int t = w; t < NTOK; t += 8) {
        float v = qf[(long)t * DQ + c];
        s += v; sq += v * v;
    }
    __shared__ float shs[8][32], shq[8][32];
    shs[w][lane] = s; shq[w][lane] = sq;
    __syncthreads();
    if (w == 0) {
        #pragma unroll
        for (int i = 1; i < 8; i++) { s += shs[i][lane]; sq += shq[i][lane]; }
        float m = s / (float)NTOK;
        float var = sq / (float)NTOK - m * m;
        mu[c] = m;
        rstd[c] = rsqrtf(var + EPS);
    }
}

__global__ void bn_apply_kernel(const float* __restrict__ qf, float* __restrict__ qn,
                                const float* __restrict__ mu, const float* __restrict__ rstd,
                                const float* __restrict__ g, const float* __restrict__ b) {
    long idx = (long)blockIdx.x * 256 + threadIdx.x;
    int c = (int)(idx & (DQ - 1));
    qn[idx] = (qf[idx] - mu[c]) * rstd[c] * g[c] + b[c];
}

// ---------------- stage-1 top-32 of 256 ----------------
__global__ void topk1_kernel(const float* __restrict__ dots,
                             float* __restrict__ s1, int* __restrict__ i1) {
    int n = blockIdx.x;
    int w = threadIdx.x >> 5;
    int lane = threadIdx.x & 31;
    const float* p = dots + ((long)w * NTOK + n) * NK;
    float v[8];
    #pragma unroll
    for (int j = 0; j < 8; j++) v[j] = p[lane + 32 * j];
    unsigned mask = 0;
    float selv = 0.f; int seli = 0;
    for (int it = 0; it < 32; it++) {
        float best = -1e30f; int bj = -1;
        #pragma unroll
        for (int j = 0; j < 8; j++)
            if (!((mask >> j) & 1u) && v[j] > best) { best = v[j]; bj = j; }
        int bidx = (bj < 0) ? 0x7fffffff : (lane + 32 * bj);
        float bv = best; int bi = bidx;
        #pragma unroll
        for (int off = 16; off; off >>= 1) {
            float ov = __shfl_xor_sync(0xffffffffu, bv, off);
            int   oi = __shfl_xor_sync(0xffffffffu, bi, off);
            if (ov > bv || (ov == bv && oi < bi)) { bv = ov; bi = oi; }
        }
        if (lane == it) { selv = bv; seli = bi; }
        if (lane == (bi & 31)) mask |= 1u << (bi >> 5);
    }
    s1[((long)n * 8 + w) * 32 + lane] = selv;
    i1[((long)n * 8 + w) * 32 + lane] = seli;
}

// ---------------- stage-2 top-32 of 32x32 + softmax ----------------
__global__ void topk2_kernel(const float* __restrict__ s1, const int* __restrict__ i1,
                             float* __restrict__ attn, int* __restrict__ vi) {
    int n = blockIdx.x;
    int h = threadIdx.x >> 5;
    int lane = threadIdx.x & 31;
    __shared__ float sv[4][32];
    __shared__ int   si[4][32];
    long base0 = ((long)n * 8 + h * 2 + 0) * 32;
    long base1 = ((long)n * 8 + h * 2 + 1) * 32;
    float s0 = s1[base0 + lane];
    int   i0 = i1[base0 + lane];
    sv[h][lane] = s1[base1 + lane];
    si[h][lane] = i1[base1 + lane];
    __syncwarp();
    unsigned mask = 0;
    float selv = 0.f; int selk = 0;
    for (int it = 0; it < 32; it++) {
        float best = -1e30f; int bj = -1;
        #pragma unroll
        for (int j = 0; j < 32; j++) {
            float val = s0 + sv[h][j];
            if (!((mask >> j) & 1u) && val > best) { best = val; bj = j; }
        }
        int key = (bj < 0) ? 0x7fffffff : (lane * 32 + bj);
        float bv = best; int bk = key;
        #pragma unroll
        for (int off = 16; off; off >>= 1) {
            float ov = __shfl_xor_sync(0xffffffffu, bv, off);
            int   ok = __shfl_xor_sync(0xffffffffu, bk, off);
            if (ov > bv || (ov == bv && ok < bk)) { bv = ov; bk = ok; }
        }
        if (lane == it) { selv = bv; selk = bk; }
        if ((bk >> 5) == lane) mask |= 1u << (bk & 31);
    }
    int wl = selk >> 5, j = selk & 31;
    int idx0 = __shfl_sync(0xffffffffu, i0, wl);
    int cart = idx0 * NK + si[h][j];
    float mx = selv;
    for (int off = 16; off; off >>= 1) mx = fmaxf(mx, __shfl_xor_sync(0xffffffffu, mx, off));
    float e = expf(selv - mx);
    float s = e;
    for (int off = 16; off; off >>= 1) s += __shfl_xor_sync(0xffffffffu, s, off);
    attn[((long)n * PH + h) * 32 + lane] = e / s;
    vi[((long)n * PH + h) * 32 + lane] = cart;
}

// ---------------- PKM gather + final residual (float4) ----------------
__global__ void __launch_bounds__(192) pkm_gather_kernel(
    const float* __restrict__ attn, const int* __restrict__ vi,
    const float* __restrict__ values,
    const float* __restrict__ x1, float* __restrict__ out) {
    int n = blockIdx.x;
    int tid = threadIdx.x;
    __shared__ float w[128];
    __shared__ int   id[128];
    if (tid < 128) {
        w[tid]  = attn[(long)n * 128 + tid];
        id[tid] = vi[(long)n * 128 + tid];
    }
    __syncthreads();
    float4 acc = *(const float4*)(x1 + (long)n * DD + tid * 4);
    #pragma unroll 4
    for (int i = 0; i < 128; i++) {
        const float4* r = (const float4*)(values + (long)id[i] * DD) + tid;
        float4 rv = *r;
        float wi = w[i];
        acc.x += wi * rv.x;
        acc.y += wi * rv.y;
        acc.z += wi * rv.z;
        acc.w += wi * rv.w;
    }
    *(float4*)(out + (long)n * DD + tid * 4) = acc;
}

// ---------------- launch ----------------
extern "C" void kernel_launch(void* const* d_in, const int* in_sizes, int n_in,
                              void* d_out, int out_size) {
    const float* x     = (const float*)d_in[0];
    const float* wq    = (const float*)d_in[1];
    const float* bq    = (const float*)d_in[2];
    const float* wk    = (const float*)d_in[3];
    const float* bk    = (const float*)d_in[4];
    const float* wv    = (const float*)d_in[5];
    const float* bv    = (const float*)d_in[6];
    const float* wo    = (const float*)d_in[7];
    const float* bo    = (const float*)d_in[8];
    const float* ln1g  = (const float*)d_in[9];
    const float* ln1b  = (const float*)d_in[10];
    const float* ln2g  = (const float*)d_in[11];
    const float* ln2b  = (const float*)d_in[12];
    const float* pkmwq = (const float*)d_in[13];
    const float* bng   = (const float*)d_in[14];
    const float* bnb   = (const float*)d_in[15];
    const float* keys  = (const float*)d_in[16];
    const float* vals  = (const float*)d_in[17];
    float* out = (float*)d_out;

    float *h1, *qb, *kb, *vb, *ctx, *x1, *h2, *qf, *qn, *mu, *rstd, *dots, *s1, *attn;
    int *i1, *viB;
    cudaGetSymbolAddress((void**)&h1, g_h1);
    cudaGetSymbolAddress((void**)&qb, g_q);
    cudaGetSymbolAddress((void**)&kb, g_k);
    cudaGetSymbolAddress((void**)&vb, g_v);
    cudaGetSymbolAddress((void**)&ctx, g_ctx);
    cudaGetSymbolAddress((void**)&x1, g_x1);
    cudaGetSymbolAddress((void**)&h2, g_h2);
    cudaGetSymbolAddress((void**)&qf, g_qf);
    cudaGetSymbolAddress((void**)&qn, g_qn);
    cudaGetSymbolAddress((void**)&mu, g_mu);
    cudaGetSymbolAddress((void**)&rstd, g_rstd);
    cudaGetSymbolAddress((void**)&dots, g_dots);
    cudaGetSymbolAddress((void**)&s1, g_s1);
    cudaGetSymbolAddress((void**)&i1, g_i1);
    cudaGetSymbolAddress((void**)&attn, g_attn);
    cudaGetSymbolAddress((void**)&viB, g_vi);

    cudaFuncSetAttribute(gemm_mma<false, 3>,
                         cudaFuncAttributeMaxDynamicSharedMemorySize, GEMM_SMEM);
    cudaFuncSetAttribute(gemm_mma<false, 1>,
                         cudaFuncAttributeMaxDynamicSharedMemorySize, GEMM_SMEM);
    cudaFuncSetAttribute(gemm_mma<true, 1>,
                         cudaFuncAttributeMaxDynamicSharedMemorySize, GEMM_SMEM);
    cudaFuncSetAttribute(flash_kernel,
                         cudaFuncAttributeMaxDynamicSharedMemorySize, FLASH_SMEM);

    const float* FN = nullptr;
    float* FNo = nullptr;

    // 1) LN1
    ln_kernel<<<NTOK, 256>>>(x, ln1g, ln1b, h1);

    // 2) fused Q/K/V projections (288 CTAs @ 2/SM -> ~1 wave)
    {
        dim3 grid(DD / 128, NTOK / 128, 3);
        gemm_mma<false, 3><<<grid, 256, GEMM_SMEM>>>(
            h1, wq, wk, wv, bq, bk, bv, FN, qb, kb, vb,
            DD, DD, DD, DD, 1, 0, 0, 0, 0, 0, 0);
    }

    // 3-5) fused flash attention -> ctx
    {
        dim3 grid(TT / 128, BB * HH);
        flash_kernel<<<grid, 256, FLASH_SMEM>>>(qb, kb, vb, ctx);
    }

    // 6) x1 = x + ctx @ wo + bo
    {
        dim3 grid(DD / 128, NTOK / 128, 1);
        gemm_mma<false, 1><<<grid, 256, GEMM_SMEM>>>(
            ctx, wo, FN, FN, bo, FN, FN, x, x1, FNo, FNo,
            DD, DD, DD, DD, 1, 0, 0, 0, 0, 0, 0);
    }

    // 7) LN2
    ln_kernel<<<NTOK, 256>>>(x1, ln2g, ln2b, h2);

    // 8) qf = h2 @ pkm_wq
    {
        dim3 grid(DQ / 128, NTOK / 128, 1);
        gemm_mma<false, 1><<<grid, 256, GEMM_SMEM>>>(
            h2, pkmwq, FN, FN, FN, FN, FN, FN, qf, FNo, FNo,
            DD, DD, DQ, DQ, 1, 0, 0, 0, 0, 0, 0);
    }

    // 9) BatchNorm over tokens
    bn_stats_kernel<<<DQ / 32, 256>>>(qf, mu, rstd);
    bn_apply_kernel<<<(NTOK * DQ) / 256, 256>>>(qf, qn, mu, rstd, bng, bnb);

    // 10) dots (256 CTAs @ 2/SM -> ~1 wave)
    {
        dim3 grid(NK / 128, NTOK / 128, PH * 2);
        long cI = (long)NTOK * NK;
        gemm_mma<true, 1><<<grid, 256, GEMM_SMEM>>>(
            qn, keys, FN, FN, FN, FN, FN, FN, dots, FNo, FNo,
            DHK, DQ, 2 * DHK, NK,
            2, DHK, PH * DHK,
            (long)NK * 2 * DHK, DHK,
            2 * cI, cI);
    }

    // 11) two-stage top-k + softmax
    topk1_kernel<<<NTOK, 256>>>(dots, s1, i1);
    topk2_kernel<<<NTOK, 128>>>(s1, i1, attn, viB);

    // 12) gather + residual -> out (float4)
    pkm_gather_kernel<<<NTOK, 192>>>(attn, viB, vals, x1, out);
}

// round 13
// speedup vs baseline: 1.1427x; 1.1427x over previous
#include <cuda_runtime.h>
#include <cuda_bf16.h>
#include <math.h>
#include <stdint.h>

// ---------------- problem dims ----------------
#define BB 2
#define TT 1024
#define DD 768
#define HH 12
#define DH 64
#define NTOK (BB*TT)          // 2048
#define PH 4
#define NK 256
#define TOPK 32
#define DHK 128
#define DQ (PH*DHK*2)         // 1024
#define EPS 1e-5f

// ---------------- scratch ----------------
__device__ float g_h1[NTOK*DD];
__device__ float g_q[NTOK*DD];
__device__ float g_k[NTOK*DD];
__device__ float g_v[NTOK*DD];
__device__ float g_ctx[NTOK*DD];
__device__ float g_x1[NTOK*DD];
__device__ float g_h2[NTOK*DD];
__device__ float g_qf[NTOK*DQ];
__device__ float g_scale[DQ];
__device__ float g_shift[DQ];
__device__ float g_dots[PH*2*NTOK*NK];
__device__ float g_attn[NTOK*PH*TOPK];
__device__ int   g_vi[NTOK*PH*TOPK];

__device__ __forceinline__ uint32_t f2tf32(float f) {
    uint32_t o;
    asm("cvt.rna.tf32.f32 %0, %1;" : "=r"(o) : "f"(f));
    return o;
}

#define MMA_TF32(d0,d1,d2,d3,a0,a1,a2,a3,b0,b1) \
    asm volatile( \
        "mma.sync.aligned.m16n8k8.row.col.f32.tf32.tf32.f32 " \
        "{%0,%1,%2,%3}, {%4,%5,%6,%7}, {%8,%9}, {%0,%1,%2,%3};" \
        : "+f"(d0), "+f"(d1), "+f"(d2), "+f"(d3) \
        : "r"(a0), "r"(a1), "r"(a2), "r"(a3), "r"(b0), "r"(b1))

extern __shared__ uint32_t dyn_smem[];

// ================= mma.sync tf32 GEMM (512 thr, double-buffered) =================
// Round-8 configuration (best measured). BNA: apply per-channel scale/shift to A at STS.
#define GEMM_SMEM ((2*128*36 + 2*128*36) * 4)

template<bool TB, int NSEL, bool BNA>
__global__ void __launch_bounds__(512, 1) gemm_mma(
    const float* __restrict__ A,
    const float* __restrict__ B0, const float* __restrict__ B1, const float* __restrict__ B2,
    const float* __restrict__ bias0, const float* __restrict__ bias1, const float* __restrict__ bias2,
    const float* __restrict__ res,
    float* __restrict__ C0, float* __restrict__ C1, float* __restrict__ C2,
    int K, int lda, int ldb, int ldc,
    int zDiv, long aO, long aI, long bO, long bI, long cO, long cI,
    const float* __restrict__ bnS, const float* __restrict__ bnB)
{
    uint32_t* As = dyn_smem;                // [2][128][36]
    uint32_t* Bs = dyn_smem + 2 * 128 * 36; // [2][128][36]

    int tid = threadIdx.x;
    const float* Bm;
    const float* bias;
    float* C;
    int chan0 = 0;
    if (NSEL == 3) {
        int s = blockIdx.z;
        Bm   = s == 0 ? B0 : (s == 1 ? B1 : B2);
        bias = s == 0 ? bias0 : (s == 1 ? bias1 : bias2);
        C    = s == 0 ? C0 : (s == 1 ? C1 : C2);
    } else {
        int z = blockIdx.z, zo = z / zDiv, zi = z - zo * zDiv;
        A  += (long)zo * aO + (long)zi * aI;
        if (BNA) chan0 = (int)(zo * aO + zi * aI);
        Bm = B0 + (long)zo * bO + (long)zi * bI;
        long coff = (long)zo * cO + (long)zi * cI;
        C = C0 + coff;
        bias = bias0;
        if (res) res += coff;
    }

    int row0 = blockIdx.y * 128, col0 = blockIdx.x * 128;

    int wid = tid >> 5, lane = tid & 31;
    int g = lane >> 2, t = lane & 3;
    int wm = wid >> 2, wn = wid & 3;
    int mbase = wm * 32, nbase = wn * 32;

    float acc[2][4][4];
    #pragma unroll
    for (int i = 0; i < 2; i++)
        #pragma unroll
        for (int j = 0; j < 4; j++)
            #pragma unroll
            for (int q = 0; q < 4; q++) acc[i][j][q] = 0.f;

    float4 ar[2];
    float4 brv[2];
    float  bsc[8];

    auto ldgA = [&](int k0) {
        #pragma unroll
        for (int i = 0; i < 2; i++) {
            int idx = i * 512 + tid;
            int r = idx >> 3, c = (idx & 7) << 2;
            ar[i] = *(const float4*)(A + (long)(row0 + r) * lda + k0 + c);
        }
    };
    auto stsA = [&](int buf, int k0) {
        uint32_t* Ab = As + buf * 128 * 36;
        #pragma unroll
        for (int i = 0; i < 2; i++) {
            int idx = i * 512 + tid;
            int r = idx >> 3, c = (idx & 7) << 2;
            float4 v = ar[i];
            if (BNA) {
                int ch = chan0 + k0 + c;
                float4 s4 = *(const float4*)(bnS + ch);
                float4 b4 = *(const float4*)(bnB + ch);
                v.x = v.x * s4.x + b4.x;
                v.y = v.y * s4.y + b4.y;
                v.z = v.z * s4.z + b4.z;
                v.w = v.w * s4.w + b4.w;
            }
            Ab[r * 36 + c + 0] = f2tf32(v.x);
            Ab[r * 36 + c + 1] = f2tf32(v.y);
            Ab[r * 36 + c + 2] = f2tf32(v.z);
            Ab[r * 36 + c + 3] = f2tf32(v.w);
        }
    };
    auto ldgB = [&](int k0) {
        if (TB) {
            #pragma unroll
            for (int i = 0; i < 2; i++) {
                int idx = i * 512 + tid;
                int r = idx >> 3, c = (idx & 7) << 2;
                brv[i] = *(const float4*)(Bm + (long)(col0 + r) * ldb + k0 + c);
            }
        } else {
            #pragma unroll
            for (int i = 0; i < 8; i++) {
                int idx = i * 512 + tid;
                int n = idx & 127, kk = idx >> 7;
                bsc[i] = Bm[(long)(k0 + kk) * ldb + col0 + n];
            }
        }
    };
    auto stsB = [&](int buf) {
        uint32_t* Bb = Bs + buf * 128 * 36;
        if (TB) {
            #pragma unroll
            for (int i = 0; i < 2; i++) {
                int idx = i * 512 + tid;
                int r = idx >> 3, c = (idx & 7) << 2;
                Bb[r * 36 + c + 0] = f2tf32(brv[i].x);
                Bb[r * 36 + c + 1] = f2tf32(brv[i].y);
                Bb[r * 36 + c + 2] = f2tf32(brv[i].z);
                Bb[r * 36 + c + 3] = f2tf32(brv[i].w);
            }
        } else {
            #pragma unroll
            for (int i = 0; i < 8; i++) {
                int idx = i * 512 + tid;
                int n = idx & 127, kk = idx >> 7;
                Bb[n * 36 + kk] = f2tf32(bsc[i]);
            }
        }
    };

    int nt = K >> 5;
    ldgA(0); ldgB(0);
    stsA(0, 0); stsB(0);
    __syncthreads();
    for (int tt = 0; tt < nt; tt++) {
        int buf = tt & 1;
        if (tt + 1 < nt) { ldgA((tt + 1) << 5); ldgB((tt + 1) << 5); }
        const uint32_t* Ab = As + buf * 128 * 36;
        const uint32_t* Bb = Bs + buf * 128 * 36;
        #pragma unroll
        for (int ks = 0; ks < 4; ks++) {
            int k0 = ks * 8;
            uint32_t af[2][4];
            #pragma unroll
            for (int i = 0; i < 2; i++) {
                int m0 = mbase + i * 16;
                af[i][0] = Ab[(m0 + g) * 36 + k0 + t];
                af[i][1] = Ab[(m0 + g + 8) * 36 + k0 + t];
                af[i][2] = Ab[(m0 + g) * 36 + k0 + t + 4];
                af[i][3] = Ab[(m0 + g + 8) * 36 + k0 + t + 4];
            }
            uint32_t bf[4][2];
            #pragma unroll
            for (int j = 0; j < 4; j++) {
                int n0 = nbase + j * 8;
                bf[j][0] = Bb[(n0 + g) * 36 + k0 + t];
                bf[j][1] = Bb[(n0 + g) * 36 + k0 + t + 4];
            }
            #pragma unroll
            for (int i = 0; i < 2; i++)
                #pragma unroll
                for (int j = 0; j < 4; j++)
                    MMA_TF32(acc[i][j][0], acc[i][j][1], acc[i][j][2], acc[i][j][3],
                             af[i][0], af[i][1], af[i][2], af[i][3],
                             bf[j][0], bf[j][1]);
        }
        if (tt + 1 < nt) { stsA(buf ^ 1, (tt + 1) << 5); stsB(buf ^ 1); }
        __syncthreads();
    }

    #pragma unroll
    for (int i = 0; i < 2; i++) {
        int r0 = row0 + mbase + i * 16 + g;
        #pragma unroll
        for (int j = 0; j < 4; j++) {
            int cc = col0 + nbase + j * 8 + t * 2;
            float2 bv = make_float2(0.f, 0.f);
            if (bias) bv = *(const float2*)(bias + cc);
            {
                long off = (long)r0 * ldc + cc;
                float2 o = make_float2(acc[i][j][0] + bv.x, acc[i][j][1] + bv.y);
                if (res) { float2 rv = *(const float2*)(res + off); o.x += rv.x; o.y += rv.y; }
                *(float2*)(C + off) = o;
            }
            {
                long off = (long)(r0 + 8) * ldc + cc;
                float2 o = make_float2(acc[i][j][2] + bv.x, acc[i][j][3] + bv.y);
                if (res) { float2 rv = *(const float2*)(res + off); o.x += rv.x; o.y += rv.y; }
                *(float2*)(C + off) = o;
            }
        }
    }
}

// ================= flash attention =================
#define LSQ 68
#define LSV 72
#define LSS 132
#define FLASH_SMEM ((128*LSQ + 128*LSQ + 128*LSV + 128*LSS + 3*128) * 4)

__global__ void __launch_bounds__(256, 1) flash_kernel(
    const float* __restrict__ q, const float* __restrict__ k,
    const float* __restrict__ v, float* __restrict__ ctx)
{
    uint32_t* Qs = dyn_smem;
    uint32_t* Ks = Qs + 128 * LSQ;
    uint32_t* Vs = Ks + 128 * LSQ;
    float*    Ss = (float*)(Vs + 128 * LSV);
    float*  rowm = Ss + 128 * LSS;
    float*  rowl = rowm + 128;
    float*  rowc = rowl + 128;

    int qt = blockIdx.x, bh = blockIdx.y;
    int b = bh / HH, h = bh % HH;
    const float* qp = q + ((long)b * TT + qt * 128) * DD + h * 64;
    const float* kp = k + (long)b * TT * DD + h * 64;
    const float* vp = v + (long)b * TT * DD + h * 64;
    float* op = ctx + ((long)b * TT + qt * 128) * DD + h * 64;

    int tid = threadIdx.x, wid = tid >> 5, lane = tid & 31;
    int g = lane >> 2, t = lane & 3;
    int wm = wid >> 1, wn = wid & 1;
    int mbase = wm * 32, nbaseS = wn * 64, nbaseO = wn * 32;

    #pragma unroll
    for (int i = 0; i < 8; i++) {
        int idx = i * 256 + tid;
        int r = idx >> 4, c = (idx & 15) << 2;
        float4 a = *(const float4*)(qp + (long)r * DD + c);
        Qs[r * LSQ + c + 0] = f2tf32(a.x);
        Qs[r * LSQ + c + 1] = f2tf32(a.y);
        Qs[r * LSQ + c + 2] = f2tf32(a.z);
        Qs[r * LSQ + c + 3] = f2tf32(a.w);
    }
    if (tid < 128) { rowm[tid] = -1e30f; rowl[tid] = 0.f; }

    float accO[2][4][4];
    #pragma unroll
    for (int i = 0; i < 2; i++)
        #pragma unroll
        for (int j = 0; j < 4; j++)
            #pragma unroll
            for (int e = 0; e < 4; e++) accO[i][j][e] = 0.f;

    for (int kt = 0; kt < 8; kt++) {
        const float* kq = kp + (long)kt * 128 * DD;
        const float* vq = vp + (long)kt * 128 * DD;
        #pragma unroll
        for (int i = 0; i < 8; i++) {
            int idx = i * 256 + tid;
            int r = idx >> 4, c = (idx & 15) << 2;
            float4 a = *(const float4*)(kq + (long)r * DD + c);
            Ks[r * LSQ + c + 0] = f2tf32(a.x);
            Ks[r * LSQ + c + 1] = f2tf32(a.y);
            Ks[r * LSQ + c + 2] = f2tf32(a.z);
            Ks[r * LSQ + c + 3] = f2tf32(a.w);
            float4 bvv = *(const float4*)(vq + (long)r * DD + c);
            Vs[r * LSV + c + 0] = f2tf32(bvv.x);
            Vs[r * LSV + c + 1] = f2tf32(bvv.y);
            Vs[r * LSV + c + 2] = f2tf32(bvv.z);
            Vs[r * LSV + c + 3] = f2tf32(bvv.w);
        }
        __syncthreads();

        float accS[2][8][4];
        #pragma unroll
        for (int i = 0; i < 2; i++)
            #pragma unroll
            for (int j = 0; j < 8; j++)
                #pragma unroll
                for (int e = 0; e < 4; e++) accS[i][j][e] = 0.f;
        #pragma unroll
        for (int ks = 0; ks < 8; ks++) {
            int k0 = ks * 8;
            uint32_t af[2][4];
            #pragma unroll
            for (int i = 0; i < 2; i++) {
                int m0 = mbase + i * 16;
                af[i][0] = Qs[(m0 + g) * LSQ + k0 + t];
                af[i][1] = Qs[(m0 + g + 8) * LSQ + k0 + t];
                af[i][2] = Qs[(m0 + g) * LSQ + k0 + t + 4];
                af[i][3] = Qs[(m0 + g + 8) * LSQ + k0 + t + 4];
            }
            uint32_t bf[8][2];
            #pragma unroll
            for (int j = 0; j < 8; j++) {
                int n0 = nbaseS + j * 8;
                bf[j][0] = Ks[(n0 + g) * LSQ + k0 + t];
                bf[j][1] = Ks[(n0 + g) * LSQ + k0 + t + 4];
            }
            #pragma unroll
            for (int i = 0; i < 2; i++)
                #pragma unroll
                for (int j = 0; j < 8; j++)
                    MMA_TF32(accS[i][j][0], accS[i][j][1], accS[i][j][2], accS[i][j][3],
                             af[i][0], af[i][1], af[i][2], af[i][3],
                             bf[j][0], bf[j][1]);
        }
        #pragma unroll
        for (int i = 0; i < 2; i++) {
            int r0 = mbase + i * 16 + g;
            #pragma unroll
            for (int j = 0; j < 8; j++) {
                int cc = nbaseS + j * 8 + t * 2;
                Ss[r0 * LSS + cc]           = accS[i][j][0] * 0.125f;
                Ss[r0 * LSS + cc + 1]       = accS[i][j][1] * 0.125f;
                Ss[(r0 + 8) * LSS + cc]     = accS[i][j][2] * 0.125f;
                Ss[(r0 + 8) * LSS + cc + 1] = accS[i][j][3] * 0.125f;
            }
        }
        __syncthreads();

        {
            int r = wid * 16 + (lane >> 1), half = lane & 1;
            float* srow = Ss + r * LSS + half * 64;
            float mx = -1e30f;
            #pragma unroll
            for (int ii = 0; ii < 16; ii++) {
                float4 a = *(float4*)(srow + ii * 4);
                mx = fmaxf(mx, fmaxf(fmaxf(a.x, a.y), fmaxf(a.z, a.w)));
            }
            mx = fmaxf(mx, __shfl_xor_sync(0xffffffffu, mx, 1));
            float mprev = rowm[r];
            float mnew = fmaxf(mprev, mx);
            float corr = __expf(mprev - mnew);
            float sum = 0.f;
            #pragma unroll
            for (int ii = 0; ii < 16; ii++) {
                float4 a = *(float4*)(srow + ii * 4);
                float p0 = __expf(a.x - mnew), p1 = __expf(a.y - mnew);
                float p2 = __expf(a.z - mnew), p3 = __expf(a.w - mnew);
                sum += p0 + p1 + p2 + p3;
                uint4 u;
                u.x = f2tf32(p0); u.y = f2tf32(p1);
                u.z = f2tf32(p2); u.w = f2tf32(p3);
                *(uint4*)(srow + ii * 4) = u;
            }
            sum += __shfl_xor_sync(0xffffffffu, sum, 1);
            if (half == 0) {
                rowm[r] = mnew;
                rowl[r] = rowl[r] * corr + sum;
                rowc[r] = corr;
            }
        }
        __syncthreads();

        float c0[2], c1[2];
        #pragma unroll
        for (int i = 0; i < 2; i++) {
            c0[i] = rowc[mbase + i * 16 + g];
            c1[i] = rowc[mbase + i * 16 + g + 8];
        }
        #pragma unroll
        for (int i = 0; i < 2; i++)
            #pragma unroll
            for (int j = 0; j < 4; j++) {
                accO[i][j][0] *= c0[i]; accO[i][j][1] *= c0[i];
                accO[i][j][2] *= c1[i]; accO[i][j][3] *= c1[i];
            }
        const uint32_t* Su = (const uint32_t*)Ss;
        #pragma unroll
        for (int ks = 0; ks < 16; ks++) {
            int k0 = ks * 8;
            uint32_t af[2][4];
            #pragma unroll
            for (int i = 0; i < 2; i++) {
                int m0 = mbase + i * 16;
                af[i][0] = Su[(m0 + g) * LSS + k0 + t];
                af[i][1] = Su[(m0 + g + 8) * LSS + k0 + t];
                af[i][2] = Su[(m0 + g) * LSS + k0 + t + 4];
                af[i][3] = Su[(m0 + g + 8) * LSS + k0 + t + 4];
            }
            uint32_t bf[4][2];
            #pragma unroll
            for (int j = 0; j < 4; j++) {
                int n0 = nbaseO + j * 8;
                bf[j][0] = Vs[(k0 + t) * LSV + n0 + g];
                bf[j][1] = Vs[(k0 + t + 4) * LSV + n0 + g];
            }
            #pragma unroll
            for (int i = 0; i < 2; i++)
                #pragma unroll
                for (int j = 0; j < 4; j++)
                    MMA_TF32(accO[i][j][0], accO[i][j][1], accO[i][j][2], accO[i][j][3],
                             af[i][0], af[i][1], af[i][2], af[i][3],
                             bf[j][0], bf[j][1]);
        }
        __syncthreads();
    }

    #pragma unroll
    for (int i = 0; i < 2; i++) {
        int r0 = mbase + i * 16 + g;
        float inv0 = 1.f / rowl[r0];
        float inv1 = 1.f / rowl[r0 + 8];
        #pragma unroll
        for (int j = 0; j < 4; j++) {
            int cc = nbaseO + j * 8 + t * 2;
            float2 o0 = make_float2(accO[i][j][0] * inv0, accO[i][j][1] * inv0);
            float2 o1 = make_float2(accO[i][j][2] * inv1, accO[i][j][3] * inv1);
            *(float2*)(op + (long)r0 * DD + cc) = o0;
            *(float2*)(op + (long)(r0 + 8) * DD + cc) = o1;
        }
    }
}

// ---------------- LayerNorm ----------------
__global__ void ln_kernel(const float* __restrict__ x, const float* __restrict__ g,
                          const float* __restrict__ b, float* __restrict__ out) {
    int n = blockIdx.x;
    int tid = threadIdx.x;
    const float* xr = x + (long)n * DD;
    float v0 = xr[tid], v1 = xr[tid + 256], v2 = xr[tid + 512];
    float s = v0 + v1 + v2;
    float sq = v0*v0 + v1*v1 + v2*v2;
    for (int off = 16; off; off >>= 1) {
        s  += __shfl_xor_sync(0xffffffffu, s, off);
        sq += __shfl_xor_sync(0xffffffffu, sq, off);
    }
    __shared__ float shs[8], shq[8];
    __shared__ float sm, sr;
    int w = tid >> 5, lane = tid & 31;
    if (lane == 0) { shs[w] = s; shq[w] = sq; }
    __syncthreads();
    if (tid == 0) {
        float ts = 0.f, tq = 0.f;
        #pragma unroll
        for (int i = 0; i < 8; i++) { ts += shs[i]; tq += shq[i]; }
        float m = ts / (float)DD;
        float var = tq / (float)DD - m * m;
        sm = m;
        sr = rsqrtf(var + EPS);
    }
    __syncthreads();
    float m = sm, rr = sr;
    float* o = out + (long)n * DD;
    o[tid]       = (v0 - m) * rr * g[tid]       + b[tid];
    o[tid + 256] = (v1 - m) * rr * g[tid + 256] + b[tid + 256];
    o[tid + 512] = (v2 - m) * rr * g[tid + 512] + b[tid + 512];
}

// ---------------- BatchNorm stats -> scale/shift ----------------
__global__ void bn_stats_kernel(const float* __restrict__ qf,
                                float* __restrict__ scale, float* __restrict__ shift,
                                const float* __restrict__ g, const float* __restrict__ b) {
    int lane = threadIdx.x & 31;
    int w = threadIdx.x >> 5;
    int c = blockIdx.x * 32 + lane;
    float s = 0.f, sq = 0.f;
    for (int t = w; t < NTOK; t += 8) {
        float v = qf[(long)t * DQ + c];
        s += v; sq += v * v;
    }
    __shared__ float shs[8][32], shq[8][32];
    shs[w][lane] = s; shq[w][lane] = sq;
    __syncthreads();
    if (w == 0) {
        #pragma unroll
        for (int i = 1; i < 8; i++) { s += shs[i][lane]; sq += shq[i][lane]; }
        float m = s / (float)NTOK;
        float var = sq / (float)NTOK - m * m;
        float rstd = rsqrtf(var + EPS);
        float sc = rstd * g[c];
        scale[c] = sc;
        shift[c] = b[c] - m * sc;
    }
}

// ---------------- fused two-stage top-k + softmax (256 thr / token) ----------------
__global__ void topk_fused_kernel(const float* __restrict__ dots,
                                  float* __restrict__ attn, int* __restrict__ vi) {
    __shared__ float sv1[8][32];
    __shared__ int   si1[8][32];
    int n = blockIdx.x;
    int w = threadIdx.x >> 5;
    int lane = threadIdx.x & 31;

    // ---- stage 1: per-z top-32 of 256 (warp w handles z=w) ----
    {
        const float* p = dots + ((long)w * NTOK + n) * NK;
        float v[8];
        #pragma unroll
        for (int j = 0; j < 8; j++) v[j] = p[lane + 32 * j];
        unsigned mask = 0;
        float selv = 0.f; int seli = 0;
        for (int it = 0; it < 32; it++) {
            float best = -1e30f; int bj = -1;
            #pragma unroll
            for (int j = 0; j < 8; j++)
                if (!((mask >> j) & 1u) && v[j] > best) { best = v[j]; bj = j; }
            int bidx = (bj < 0) ? 0x7fffffff : (lane + 32 * bj);
            float bv = best; int bi = bidx;
            #pragma unroll
            for (int off = 16; off; off >>= 1) {
                float ov = __shfl_xor_sync(0xffffffffu, bv, off);
                int   oi = __shfl_xor_sync(0xffffffffu, bi, off);
                if (ov > bv || (ov == bv && oi < bi)) { bv = ov; bi = oi; }
            }
            if (lane == it) { selv = bv; seli = bi; }
            if (lane == (bi & 31)) mask |= 1u << (bi >> 5);
        }
        sv1[w][lane] = selv;
        si1[w][lane] = seli;
    }
    __syncthreads();

    // ---- stage 2: per-head top-32 of 32x32 combos + softmax (warps 0..3) ----
    if (threadIdx.x < 128) {
        int h = w;  // 0..3
        float s0 = sv1[h * 2][lane];
        int   i0 = si1[h * 2][lane];
        unsigned mask = 0;
        float selv = 0.f; int selk = 0;
        for (int it = 0; it < 32; it++) {
            float best = -1e30f; int bj = -1;
            #pragma unroll
            for (int j = 0; j < 32; j++) {
                float val = s0 + sv1[h * 2 + 1][j];
                if (!((mask >> j) & 1u) && val > best) { best = val; bj = j; }
            }
            int key = (bj < 0) ? 0x7fffffff : (lane * 32 + bj);
            float bv = best; int bk = key;
            #pragma unroll
            for (int off = 16; off; off >>= 1) {
                float ov = __shfl_xor_sync(0xffffffffu, bv, off);
                int   ok = __shfl_xor_sync(0xffffffffu, bk, off);
                if (ov > bv || (ov == bv && ok < bk)) { bv = ov; bk = ok; }
            }
            if (lane == it) { selv = bv; selk = bk; }
            if ((bk >> 5) == lane) mask |= 1u << (bk & 31);
        }
        int wl = selk >> 5, j = selk & 31;
        int idx0 = __shfl_sync(0xffffffffu, i0, wl);
        int cart = idx0 * NK + si1[h * 2 + 1][j];
        float mx = selv;
        for (int off = 16; off; off >>= 1) mx = fmaxf(mx, __shfl_xor_sync(0xffffffffu, mx, off));
        float e = expf(selv - mx);
        float s = e;
        for (int off = 16; off; off >>= 1) s += __shfl_xor_sync(0xffffffffu, s, off);
        attn[((long)n * PH + h) * 32 + lane] = e / s;
        vi[((long)n * PH + h) * 32 + lane] = cart;
    }
}

// ---------------- PKM gather + final residual (float4) ----------------
__global__ void __launch_bounds__(192) pkm_gather_kernel(
    const float* __restrict__ attn, const int* __restrict__ vi,
    const float* __restrict__ values,
    const float* __restrict__ x1, float* __restrict__ out) {
    int n = blockIdx.x;
    int tid = threadIdx.x;
    __shared__ float w[128];
    __shared__ int   id[128];
    if (tid < 128) {
        w[tid]  = attn[(long)n * 128 + tid];
        id[tid] = vi[(long)n * 128 + tid];
    }
    __syncthreads();
    float4 acc = *(const float4*)(x1 + (long)n * DD + tid * 4);
    #pragma unroll 8
    for (int i = 0; i < 128; i++) {
        const float4* r = (const float4*)(values + (long)id[i] * DD) + tid;
        float4 rv = *r;
        float wi = w[i];
        acc.x += wi * rv.x;
        acc.y += wi * rv.y;
        acc.z += wi * rv.z;
        acc.w += wi * rv.w;
    }
    *(float4*)(out + (long)n * DD + tid * 4) = acc;
}

// ---------------- launch ----------------
extern "C" void kernel_launch(void* const* d_in, const int* in_sizes, int n_in,
                              void* d_out, int out_size) {
    const float* x     = (const float*)d_in[0];
    const float* wq    = (const float*)d_in[1];
    const float* bq    = (const float*)d_in[2];
    const float* wk    = (const float*)d_in[3];
    const float* bk    = (const float*)d_in[4];
    const float* wv    = (const float*)d_in[5];
    const float* bv    = (const float*)d_in[6];
    const float* wo    = (const float*)d_in[7];
    const float* bo    = (const float*)d_in[8];
    const float* ln1g  = (const float*)d_in[9];
    const float* ln1b  = (const float*)d_in[10];
    const float* ln2g  = (const float*)d_in[11];
    const float* ln2b  = (const float*)d_in[12];
    const float* pkmwq = (const float*)d_in[13];
    const float* bng   = (const float*)d_in[14];
    const float* bnb   = (const float*)d_in[15];
    const float* keys  = (const float*)d_in[16];
    const float* vals  = (const float*)d_in[17];
    float* out = (float*)d_out;

    float *h1, *qb, *kb, *vb, *ctx, *x1, *h2, *qf, *scl, *shf, *dots, *attn;
    int *viB;
    cudaGetSymbolAddress((void**)&h1, g_h1);
    cudaGetSymbolAddress((void**)&qb, g_q);
    cudaGetSymbolAddress((void**)&kb, g_k);
    cudaGetSymbolAddress((void**)&vb, g_v);
    cudaGetSymbolAddress((void**)&ctx, g_ctx);
    cudaGetSymbolAddress((void**)&x1, g_x1);
    cudaGetSymbolAddress((void**)&h2, g_h2);
    cudaGetSymbolAddress((void**)&qf, g_qf);
    cudaGetSymbolAddress((void**)&scl, g_scale);
    cudaGetSymbolAddress((void**)&shf, g_shift);
    cudaGetSymbolAddress((void**)&dots, g_dots);
    cudaGetSymbolAddress((void**)&attn, g_attn);
    cudaGetSymbolAddress((void**)&viB, g_vi);

    cudaFuncSetAttribute(gemm_mma<false, 3, false>,
                         cudaFuncAttributeMaxDynamicSharedMemorySize, GEMM_SMEM);
    cudaFuncSetAttribute(gemm_mma<false, 1, false>,
                         cudaFuncAttributeMaxDynamicSharedMemorySize, GEMM_SMEM);
    cudaFuncSetAttribute(gemm_mma<true, 1, true>,
                         cudaFuncAttributeMaxDynamicSharedMemorySize, GEMM_SMEM);
    cudaFuncSetAttribute(flash_kernel,
                         cudaFuncAttributeMaxDynamicSharedMemorySize, FLASH_SMEM);

    const float* FN = nullptr;
    float* FNo = nullptr;

    // 1) LN1
    ln_kernel<<<NTOK, 256>>>(x, ln1g, ln1b, h1);

    // 2) fused Q/K/V projections
    {
        dim3 grid(DD / 128, NTOK / 128, 3);
        gemm_mma<false, 3, false><<<grid, 512, GEMM_SMEM>>>(
            h1, wq, wk, wv, bq, bk, bv, FN, qb, kb, vb,
            DD, DD, DD, DD, 1, 0, 0, 0, 0, 0, 0, FN, FN);
    }

    // 3-5) fused flash attention -> ctx
    {
        dim3 grid(TT / 128, BB * HH);
        flash_kernel<<<grid, 256, FLASH_SMEM>>>(qb, kb, vb, ctx);
    }

    // 6) x1 = x + ctx @ wo + bo
    {
        dim3 grid(DD / 128, NTOK / 128, 1);
        gemm_mma<false, 1, false><<<grid, 512, GEMM_SMEM>>>(
            ctx, wo, FN, FN, bo, FN, FN, x, x1, FNo, FNo,
            DD, DD, DD, DD, 1, 0, 0, 0, 0, 0, 0, FN, FN);
    }

    // 7) LN2
    ln_kernel<<<NTOK, 256>>>(x1, ln2g, ln2b, h2);

    // 8) qf = h2 @ pkm_wq
    {
        dim3 grid(DQ / 128, NTOK / 128, 1);
        gemm_mma<false, 1, false><<<grid, 512, GEMM_SMEM>>>(
            h2, pkmwq, FN, FN, FN, FN, FN, FN, qf, FNo, FNo,
            DD, DD, DQ, DQ, 1, 0, 0, 0, 0, 0, 0, FN, FN);
    }

    // 9) BatchNorm stats -> scale/shift (apply fused into dots GEMM)
    bn_stats_kernel<<<DQ / 32, 256>>>(qf, scl, shf, bng, bnb);

    // 10) dots = BN(qf) @ keys^T  (BN fused into A-path)
    {
        dim3 grid(NK / 128, NTOK / 128, PH * 2);
        long cI = (long)NTOK * NK;
        gemm_mma<true, 1, true><<<grid, 512, GEMM_SMEM>>>(
            qf, keys, FN, FN, FN, FN, FN, FN, dots, FNo, FNo,
            DHK, DQ, 2 * DHK, NK,
            2, DHK, PH * DHK,
            (long)NK * 2 * DHK, DHK,
            2 * cI, cI, scl, shf);
    }

    // 11) fused two-stage top-k + softmax
    topk_fused_kernel<<<NTOK, 256>>>(dots, attn, viB);

    // 12) gather + residual -> out (float4)
    pkm_gather_kernel<<<NTOK, 192>>>(attn, viB, vals, x1, out);
}